// round 9
// baseline (speedup 1.0000x reference)
#include <cuda_runtime.h>
#include <math_constants.h>
#include <cstdint>

// Problem constants
#define S_LEN 1024
#define B_SZ  8
#define H_DIM 1024
#define NHEAD 16
#define HDIM  64
#define M_ROWS (B_SZ * S_LEN)   // 8192

// Scratch for projected Q/K/V, [B*S, H] with m = b*S_LEN + s.
__device__ float g_QL[(size_t)M_ROWS * H_DIM];
__device__ float g_KL[(size_t)M_ROWS * H_DIM];
__device__ float g_VL[(size_t)M_ROWS * H_DIM];

// ---------------------------------------------------------------------------
// Packed fp32x2 helpers
// ---------------------------------------------------------------------------
__device__ __forceinline__ unsigned long long ffma2(
    unsigned long long a, unsigned long long b, unsigned long long c)
{
    unsigned long long d;
    asm("fma.rn.f32x2 %0, %1, %2, %3;" : "=l"(d) : "l"(a), "l"(b), "l"(c));
    return d;
}
__device__ __forceinline__ unsigned long long pack2(float x)
{
    unsigned long long d;
    asm("mov.b64 %0, {%1, %1};" : "=l"(d) : "f"(x));
    return d;
}
__device__ __forceinline__ void unpack2(unsigned long long v, float& lo, float& hi)
{
    asm("mov.b64 {%0, %1}, %2;" : "=f"(lo), "=f"(hi) : "l"(v));
}

// ---------------------------------------------------------------------------
// Projection GEMM (proven R5 version): Y[m][n] = sum_k X'[m][k]*W[n][k] + b[n]
//   128x128 tile, BK=16, 256 threads, 8x8 per thread, f32x2 inner loop.
// ---------------------------------------------------------------------------
__global__ __launch_bounds__(256, 2) void proj_kernel(
    const float* __restrict__ X, const float* __restrict__ W,
    const float* __restrict__ bias, int which)
{
    float* out = (which == 0) ? g_QL : ((which == 1) ? g_KL : g_VL);

    const int BK = 16;
    __shared__ float As[BK][132];
    __shared__ float Bs[BK][132];

    const int m0 = blockIdx.y * 128;
    const int n0 = blockIdx.x * 128;
    const int tid = threadIdx.x;
    const int tx = tid & 15;
    const int ty = tid >> 4;

    unsigned long long acc[8][4];
    #pragma unroll
    for (int i = 0; i < 8; i++)
        #pragma unroll
        for (int j = 0; j < 4; j++) acc[i][j] = 0ull;

    for (int k0 = 0; k0 < H_DIM; k0 += BK) {
        #pragma unroll
        for (int l = 0; l < 2; l++) {
            int f  = l * 256 + tid;
            int r  = f >> 2;
            int c4 = f & 3;
            int m  = m0 + r;
            int b  = m >> 10;
            int s  = m & 1023;
            const float4 v = *reinterpret_cast<const float4*>(
                X + ((size_t)(s * B_SZ + b)) * H_DIM + k0 + c4 * 4);
            As[c4 * 4 + 0][r] = v.x; As[c4 * 4 + 1][r] = v.y;
            As[c4 * 4 + 2][r] = v.z; As[c4 * 4 + 3][r] = v.w;
        }
        #pragma unroll
        for (int l = 0; l < 2; l++) {
            int f  = l * 256 + tid;
            int r  = f >> 2;
            int c4 = f & 3;
            const float4 v = *reinterpret_cast<const float4*>(
                W + (size_t)(n0 + r) * H_DIM + k0 + c4 * 4);
            Bs[c4 * 4 + 0][r] = v.x; Bs[c4 * 4 + 1][r] = v.y;
            Bs[c4 * 4 + 2][r] = v.z; Bs[c4 * 4 + 3][r] = v.w;
        }
        __syncthreads();

        #pragma unroll
        for (int kk = 0; kk < BK; kk++) {
            float4 a0 = *reinterpret_cast<const float4*>(&As[kk][ty * 8]);
            float4 a1 = *reinterpret_cast<const float4*>(&As[kk][ty * 8 + 4]);
            unsigned long long aa[8];
            aa[0] = pack2(a0.x); aa[1] = pack2(a0.y); aa[2] = pack2(a0.z); aa[3] = pack2(a0.w);
            aa[4] = pack2(a1.x); aa[5] = pack2(a1.y); aa[6] = pack2(a1.z); aa[7] = pack2(a1.w);
            const unsigned long long* bp =
                reinterpret_cast<const unsigned long long*>(&Bs[kk][tx * 8]);
            unsigned long long b0 = bp[0], b1 = bp[1], b2 = bp[2], b3 = bp[3];
            #pragma unroll
            for (int i = 0; i < 8; i++) {
                acc[i][0] = ffma2(aa[i], b0, acc[i][0]);
                acc[i][1] = ffma2(aa[i], b1, acc[i][1]);
                acc[i][2] = ffma2(aa[i], b2, acc[i][2]);
                acc[i][3] = ffma2(aa[i], b3, acc[i][3]);
            }
        }
        __syncthreads();
    }

    const float4 bsv0 = *reinterpret_cast<const float4*>(bias + n0 + tx * 8);
    const float4 bsv1 = *reinterpret_cast<const float4*>(bias + n0 + tx * 8 + 4);
    #pragma unroll
    for (int i = 0; i < 8; i++) {
        int m = m0 + ty * 8 + i;
        float lo, hi;
        float4 o0, o1;
        unpack2(acc[i][0], lo, hi); o0.x = lo + bsv0.x; o0.y = hi + bsv0.y;
        unpack2(acc[i][1], lo, hi); o0.z = lo + bsv0.z; o0.w = hi + bsv0.w;
        unpack2(acc[i][2], lo, hi); o1.x = lo + bsv1.x; o1.y = hi + bsv1.y;
        unpack2(acc[i][3], lo, hi); o1.z = lo + bsv1.z; o1.w = hi + bsv1.w;
        float* op = out + (size_t)m * H_DIM + n0 + tx * 8;
        *reinterpret_cast<float4*>(op)     = o0;
        *reinterpret_cast<float4*>(op + 4) = o1;
    }
}

// ---------------------------------------------------------------------------
// Fused attention, restructured for fewer syncs / less smem traffic:
//   - Q tile (128 x 64) loaded into smem ONCE per CTA (was 8x).
//   - K tile (128 x 64) loaded once per kt; single 64-deep kk loop
//     (2 syncs per kt instead of 8).
//   - Phase 2 in 64-deep chunks (2 syncs per chunk instead of 8), P-staging
//     and V tile aliased into the phase-1 smem regions.
// Dynamic smem: 17152 floats = 68608 B -> 2 CTAs/SM.
// ---------------------------------------------------------------------------
#define SMQ_OFF 0              // 64 x 132 floats (also phase-2 P tile)
#define SMK_OFF 8448           // 64 x 132 floats (also phase-2 V tile, 64x68)
#define SMM_OFF 16896          // 128 floats row max
#define SMI_OFF 17024          // 128 floats 1/l
#define ATTN_SMEM_FLOATS 17152
#define ATTN_SMEM_BYTES (ATTN_SMEM_FLOATS * 4)

__global__ __launch_bounds__(256, 2) void attn_kernel(
    const int* __restrict__ mask, float* w, float* out_ctx)
{
    extern __shared__ float sm[];
    float* smQ  = sm + SMQ_OFF;
    float* smK  = sm + SMK_OFF;
    float* smM  = sm + SMM_OFF;
    float* smIL = sm + SMI_OFF;

    const int bh = blockIdx.y;
    const int b = bh >> 4;
    const int h = bh & 15;
    const int q0 = blockIdx.x * 128;
    const float* Qb = g_QL + (size_t)b * S_LEN * H_DIM + h * HDIM;
    const float* Kb = g_KL + (size_t)b * S_LEN * H_DIM + h * HDIM;
    const float* Vb = g_VL + (size_t)b * S_LEN * H_DIM + h * HDIM;
    float* W = w + (size_t)bh * S_LEN * S_LEN;

    const int tid = threadIdx.x;
    const int tx = tid & 15;
    const int ty = tid >> 4;
    const int sr = tid >> 1;      // staging row (2 threads/row)
    const int hf = tid & 1;

    float row_m[8], row_l[8];
    #pragma unroll
    for (int i = 0; i < 8; i++) { row_m[i] = -CUDART_INF_F; row_l[i] = 0.0f; }

    // ---- Load Q tile once: [k 0..63][m 0..127], row stride 132 ----
    {
        const float* qp = Qb + (size_t)(q0 + sr) * H_DIM + hf * 32;
        #pragma unroll
        for (int i = 0; i < 8; i++) {
            float4 v = *reinterpret_cast<const float4*>(qp + i * 4);
            int k = hf * 32 + i * 4;
            smQ[(k + 0) * 132 + sr] = v.x;
            smQ[(k + 1) * 132 + sr] = v.y;
            smQ[(k + 2) * 132 + sr] = v.z;
            smQ[(k + 3) * 132 + sr] = v.w;
        }
    }

    // ---------------- Phase 1: scores + online stats ----------------
    for (int kt = 0; kt < 8; kt++) {
        const int n0 = kt * 128;

        // K tile: [k][n] scatter, same pattern as Q
        {
            const float* kp = Kb + (size_t)(n0 + sr) * H_DIM + hf * 32;
            #pragma unroll
            for (int i = 0; i < 8; i++) {
                float4 v = *reinterpret_cast<const float4*>(kp + i * 4);
                int k = hf * 32 + i * 4;
                smK[(k + 0) * 132 + sr] = v.x;
                smK[(k + 1) * 132 + sr] = v.y;
                smK[(k + 2) * 132 + sr] = v.z;
                smK[(k + 3) * 132 + sr] = v.w;
            }
        }
        __syncthreads();

        unsigned long long acc[8][4];
        #pragma unroll
        for (int i = 0; i < 8; i++)
            #pragma unroll
            for (int j = 0; j < 4; j++) acc[i][j] = 0ull;

        #pragma unroll 8
        for (int kk = 0; kk < HDIM; kk++) {
            float4 a0 = *reinterpret_cast<const float4*>(&smQ[kk * 132 + ty * 8]);
            float4 a1 = *reinterpret_cast<const float4*>(&smQ[kk * 132 + ty * 8 + 4]);
            unsigned long long aa[8];
            aa[0] = pack2(a0.x); aa[1] = pack2(a0.y); aa[2] = pack2(a0.z); aa[3] = pack2(a0.w);
            aa[4] = pack2(a1.x); aa[5] = pack2(a1.y); aa[6] = pack2(a1.z); aa[7] = pack2(a1.w);
            const unsigned long long* bp =
                reinterpret_cast<const unsigned long long*>(&smK[kk * 132 + tx * 8]);
            unsigned long long b0 = bp[0], b1 = bp[1], b2 = bp[2], b3 = bp[3];
            #pragma unroll
            for (int i = 0; i < 8; i++) {
                acc[i][0] = ffma2(aa[i], b0, acc[i][0]);
                acc[i][1] = ffma2(aa[i], b1, acc[i][1]);
                acc[i][2] = ffma2(aa[i], b2, acc[i][2]);
                acc[i][3] = ffma2(aa[i], b3, acc[i][3]);
            }
        }
        __syncthreads();   // before next kt overwrites smK

        // scale + mask
        float madd[8];
        #pragma unroll
        for (int j = 0; j < 8; j++) {
            int n = n0 + tx * 8 + j;
            madd[j] = (mask[b * S_LEN + n] != 0) ? -1000000.0f : 0.0f;
        }

        float sacc[8][8];
        #pragma unroll
        for (int i = 0; i < 8; i++) {
            #pragma unroll
            for (int jj = 0; jj < 4; jj++) {
                float lo, hi;
                unpack2(acc[i][jj], lo, hi);
                sacc[i][2 * jj]     = lo * 0.125f + madd[2 * jj];
                sacc[i][2 * jj + 1] = hi * 0.125f + madd[2 * jj + 1];
            }
        }

        // online stats across the 16 tx lanes + raw float4 store
        #pragma unroll
        for (int i = 0; i < 8; i++) {
            float tm = sacc[i][0];
            #pragma unroll
            for (int j = 1; j < 8; j++) tm = fmaxf(tm, sacc[i][j]);
            #pragma unroll
            for (int o = 8; o > 0; o >>= 1)
                tm = fmaxf(tm, __shfl_xor_sync(0xffffffffu, tm, o));
            float ts = 0.0f;
            #pragma unroll
            for (int j = 0; j < 8; j++) ts += __expf(sacc[i][j] - tm);
            #pragma unroll
            for (int o = 8; o > 0; o >>= 1)
                ts += __shfl_xor_sync(0xffffffffu, ts, o);

            float mn = fmaxf(row_m[i], tm);
            row_l[i] = row_l[i] * __expf(row_m[i] - mn) + ts * __expf(tm - mn);
            row_m[i] = mn;

            float4 s0 = make_float4(sacc[i][0], sacc[i][1], sacc[i][2], sacc[i][3]);
            float4 s1 = make_float4(sacc[i][4], sacc[i][5], sacc[i][6], sacc[i][7]);
            float* wp = W + (size_t)(q0 + ty * 8 + i) * S_LEN + n0 + tx * 8;
            *reinterpret_cast<float4*>(wp)     = s0;
            *reinterpret_cast<float4*>(wp + 4) = s1;
        }
    }

    if (tx == 0) {
        #pragma unroll
        for (int i = 0; i < 8; i++) {
            smM[ty * 8 + i]  = row_m[i];
            smIL[ty * 8 + i] = 1.0f / row_l[i];
        }
    }
    __syncthreads();

    // ---------------- Phase 2: normalize (final weights) + P*V ----------
    // smP aliases smQ region (64 x 132); smV aliases smK region (64 x 68).
    float* smP = smQ;
    float* smV = smK;

    unsigned long long cacc[8][2];
    #pragma unroll
    for (int i = 0; i < 8; i++) { cacc[i][0] = 0ull; cacc[i][1] = 0ull; }

    for (int k0 = 0; k0 < S_LEN; k0 += 64) {
        // P staging: read raw, normalize, write back, scatter [k][m]
        {
            const float mm = smM[sr];
            const float il = smIL[sr];
            float* wrow = W + (size_t)(q0 + sr) * S_LEN + k0 + hf * 32;
            #pragma unroll
            for (int i = 0; i < 8; i++) {
                float4 v = *reinterpret_cast<float4*>(wrow + i * 4);
                v.x = __expf(v.x - mm) * il;
                v.y = __expf(v.y - mm) * il;
                v.z = __expf(v.z - mm) * il;
                v.w = __expf(v.w - mm) * il;
                *reinterpret_cast<float4*>(wrow + i * 4) = v;
                int k = hf * 32 + i * 4;
                smP[(k + 0) * 132 + sr] = v.x;
                smP[(k + 1) * 132 + sr] = v.y;
                smP[(k + 2) * 132 + sr] = v.z;
                smP[(k + 3) * 132 + sr] = v.w;
            }
        }
        // V tile: 64 rows x 64 cols, row stride 68
        #pragma unroll
        for (int lp = 0; lp < 4; lp++) {
            int f = lp * 256 + tid;
            int r = f >> 4, c = f & 15;
            const float4 v = *reinterpret_cast<const float4*>(
                Vb + (size_t)(k0 + r) * H_DIM + c * 4);
            *reinterpret_cast<float4*>(&smV[r * 68 + c * 4]) = v;
        }
        __syncthreads();

        #pragma unroll 8
        for (int kk = 0; kk < 64; kk++) {
            float4 a0 = *reinterpret_cast<const float4*>(&smP[kk * 132 + ty * 8]);
            float4 a1 = *reinterpret_cast<const float4*>(&smP[kk * 132 + ty * 8 + 4]);
            unsigned long long aa[8];
            aa[0] = pack2(a0.x); aa[1] = pack2(a0.y); aa[2] = pack2(a0.z); aa[3] = pack2(a0.w);
            aa[4] = pack2(a1.x); aa[5] = pack2(a1.y); aa[6] = pack2(a1.z); aa[7] = pack2(a1.w);
            const unsigned long long* bp =
                reinterpret_cast<const unsigned long long*>(&smV[kk * 68 + tx * 4]);
            unsigned long long b0 = bp[0], b1 = bp[1];
            #pragma unroll
            for (int i = 0; i < 8; i++) {
                cacc[i][0] = ffma2(aa[i], b0, cacc[i][0]);
                cacc[i][1] = ffma2(aa[i], b1, cacc[i][1]);
            }
        }
        __syncthreads();
    }

    // write ctx in [S, B, H] layout
    #pragma unroll
    for (int i = 0; i < 8; i++) {
        int s = q0 + ty * 8 + i;
        float lo, hi;
        float4 o;
        unpack2(cacc[i][0], lo, hi); o.x = lo; o.y = hi;
        unpack2(cacc[i][1], lo, hi); o.z = lo; o.w = hi;
        *reinterpret_cast<float4*>(
            out_ctx + ((size_t)s * B_SZ + b) * H_DIM + h * HDIM + tx * 4) = o;
    }
}

// ---------------------------------------------------------------------------
// Launch
// ---------------------------------------------------------------------------
extern "C" void kernel_launch(void* const* d_in, const int* in_sizes, int n_in,
                              void* d_out, int out_size)
{
    const float* q_states = (const float*)d_in[0];
    const float* k_states = (const float*)d_in[1];
    const float* v_states = (const float*)d_in[2];
    const int*   mask     = (const int*)  d_in[3];
    const float* Wq = (const float*)d_in[4];
    const float* bq = (const float*)d_in[5];
    const float* Wk = (const float*)d_in[6];
    const float* bk = (const float*)d_in[7];
    const float* Wv = (const float*)d_in[8];
    const float* bv = (const float*)d_in[9];

    float* out_ctx = (float*)d_out;                           // [S, B, H]
    float* out_w   = out_ctx + (size_t)S_LEN * B_SZ * H_DIM;  // [B, NH, S, S]

    // Host-side attribute set; idempotent, capture-safe (not a stream op).
    static int smem_set = 0;
    if (!smem_set) {
        cudaFuncSetAttribute(attn_kernel,
                             cudaFuncAttributeMaxDynamicSharedMemorySize,
                             ATTN_SMEM_BYTES);
        smem_set = 1;
    }

    dim3 pg(H_DIM / 128, M_ROWS / 128);      // (8, 64)
    proj_kernel<<<pg, 256>>>(q_states, Wq, bq, 0);
    proj_kernel<<<pg, 256>>>(k_states, Wk, bk, 1);
    proj_kernel<<<pg, 256>>>(v_states, Wv, bv, 2);

    dim3 ag(S_LEN / 128, B_SZ * NHEAD);      // (8, 128)
    attn_kernel<<<ag, 256, ATTN_SMEM_BYTES>>>(mask, out_w, out_ctx);
}

// round 10
// speedup vs baseline: 1.7253x; 1.7253x over previous
#include <cuda_runtime.h>
#include <math_constants.h>
#include <cstdint>

// Problem constants
#define S_LEN 1024
#define B_SZ  8
#define H_DIM 1024
#define NHEAD 16
#define HDIM  64
#define M_ROWS (B_SZ * S_LEN)   // 8192

// Scratch for projected Q/K/V, [B*S, H] with m = b*S_LEN + s.
__device__ float g_QL[(size_t)M_ROWS * H_DIM];
__device__ float g_KL[(size_t)M_ROWS * H_DIM];
__device__ float g_VL[(size_t)M_ROWS * H_DIM];

// ---------------------------------------------------------------------------
// Packed fp32x2 helpers
// ---------------------------------------------------------------------------
__device__ __forceinline__ unsigned long long ffma2(
    unsigned long long a, unsigned long long b, unsigned long long c)
{
    unsigned long long d;
    asm("fma.rn.f32x2 %0, %1, %2, %3;" : "=l"(d) : "l"(a), "l"(b), "l"(c));
    return d;
}
__device__ __forceinline__ unsigned long long pack2(float x)
{
    unsigned long long d;
    asm("mov.b64 %0, {%1, %1};" : "=l"(d) : "f"(x));
    return d;
}
__device__ __forceinline__ void unpack2(unsigned long long v, float& lo, float& hi)
{
    asm("mov.b64 {%0, %1}, %2;" : "=f"(lo), "=f"(hi) : "l"(v));
}

// ---------------------------------------------------------------------------
// Merged projection GEMM (proven R5 inner body; one launch, grid.z selects
// which projection): Y[m][n] = sum_k X'[m][k]*W[n][k] + b[n]
//   128x128 tile, BK=16, 256 threads, 8x8 per thread, f32x2 inner loop.
//   grid = (8, 64, 3)
// ---------------------------------------------------------------------------
__global__ __launch_bounds__(256, 2) void proj_kernel(
    const float* __restrict__ Xq, const float* __restrict__ Xk,
    const float* __restrict__ Xv,
    const float* __restrict__ Wq, const float* __restrict__ bq,
    const float* __restrict__ Wk, const float* __restrict__ bk,
    const float* __restrict__ Wv, const float* __restrict__ bv)
{
    const int z = blockIdx.z;
    const float* X    = (z == 0) ? Xq : ((z == 1) ? Xk : Xv);
    const float* W    = (z == 0) ? Wq : ((z == 1) ? Wk : Wv);
    const float* bias = (z == 0) ? bq : ((z == 1) ? bk : bv);
    float* out        = (z == 0) ? g_QL : ((z == 1) ? g_KL : g_VL);

    const int BK = 16;
    __shared__ float As[BK][132];
    __shared__ float Bs[BK][132];

    const int m0 = blockIdx.y * 128;
    const int n0 = blockIdx.x * 128;
    const int tid = threadIdx.x;
    const int tx = tid & 15;
    const int ty = tid >> 4;

    unsigned long long acc[8][4];
    #pragma unroll
    for (int i = 0; i < 8; i++)
        #pragma unroll
        for (int j = 0; j < 4; j++) acc[i][j] = 0ull;

    for (int k0 = 0; k0 < H_DIM; k0 += BK) {
        #pragma unroll
        for (int l = 0; l < 2; l++) {
            int f  = l * 256 + tid;
            int r  = f >> 2;
            int c4 = f & 3;
            int m  = m0 + r;
            int b  = m >> 10;
            int s  = m & 1023;
            const float4 v = *reinterpret_cast<const float4*>(
                X + ((size_t)(s * B_SZ + b)) * H_DIM + k0 + c4 * 4);
            As[c4 * 4 + 0][r] = v.x; As[c4 * 4 + 1][r] = v.y;
            As[c4 * 4 + 2][r] = v.z; As[c4 * 4 + 3][r] = v.w;
        }
        #pragma unroll
        for (int l = 0; l < 2; l++) {
            int f  = l * 256 + tid;
            int r  = f >> 2;
            int c4 = f & 3;
            const float4 v = *reinterpret_cast<const float4*>(
                W + (size_t)(n0 + r) * H_DIM + k0 + c4 * 4);
            Bs[c4 * 4 + 0][r] = v.x; Bs[c4 * 4 + 1][r] = v.y;
            Bs[c4 * 4 + 2][r] = v.z; Bs[c4 * 4 + 3][r] = v.w;
        }
        __syncthreads();

        #pragma unroll
        for (int kk = 0; kk < BK; kk++) {
            float4 a0 = *reinterpret_cast<const float4*>(&As[kk][ty * 8]);
            float4 a1 = *reinterpret_cast<const float4*>(&As[kk][ty * 8 + 4]);
            unsigned long long aa[8];
            aa[0] = pack2(a0.x); aa[1] = pack2(a0.y); aa[2] = pack2(a0.z); aa[3] = pack2(a0.w);
            aa[4] = pack2(a1.x); aa[5] = pack2(a1.y); aa[6] = pack2(a1.z); aa[7] = pack2(a1.w);
            const unsigned long long* bp =
                reinterpret_cast<const unsigned long long*>(&Bs[kk][tx * 8]);
            unsigned long long b0 = bp[0], b1 = bp[1], b2 = bp[2], b3 = bp[3];
            #pragma unroll
            for (int i = 0; i < 8; i++) {
                acc[i][0] = ffma2(aa[i], b0, acc[i][0]);
                acc[i][1] = ffma2(aa[i], b1, acc[i][1]);
                acc[i][2] = ffma2(aa[i], b2, acc[i][2]);
                acc[i][3] = ffma2(aa[i], b3, acc[i][3]);
            }
        }
        __syncthreads();
    }

    const float4 bsv0 = *reinterpret_cast<const float4*>(bias + n0 + tx * 8);
    const float4 bsv1 = *reinterpret_cast<const float4*>(bias + n0 + tx * 8 + 4);
    #pragma unroll
    for (int i = 0; i < 8; i++) {
        int m = m0 + ty * 8 + i;
        float lo, hi;
        float4 o0, o1;
        unpack2(acc[i][0], lo, hi); o0.x = lo + bsv0.x; o0.y = hi + bsv0.y;
        unpack2(acc[i][1], lo, hi); o0.z = lo + bsv0.z; o0.w = hi + bsv0.w;
        unpack2(acc[i][2], lo, hi); o1.x = lo + bsv1.x; o1.y = hi + bsv1.y;
        unpack2(acc[i][3], lo, hi); o1.z = lo + bsv1.z; o1.w = hi + bsv1.w;
        float* op = out + (size_t)m * H_DIM + n0 + tx * 8;
        *reinterpret_cast<float4*>(op)     = o0;
        *reinterpret_cast<float4*>(op + 4) = o1;
    }
}

// ---------------------------------------------------------------------------
// Fused attention (byte-exact R5 version, proven 2390us): per (bh, q-tile 128):
//   Phase 1: S = QK^T/8 + mask -> raw to W, online row max/sum.
//   Phase 2: normalize in place (final attn_weights) + P*V -> ctx.
// ---------------------------------------------------------------------------
__global__ __launch_bounds__(256, 2) void attn_kernel(
    const int* __restrict__ mask, float* w, float* out_ctx)
{
    const int bh = blockIdx.y;
    const int b = bh >> 4;
    const int h = bh & 15;
    const int q0 = blockIdx.x * 128;
    const float* Qb = g_QL + (size_t)b * S_LEN * H_DIM + h * HDIM;
    const float* Kb = g_KL + (size_t)b * S_LEN * H_DIM + h * HDIM;
    const float* Vb = g_VL + (size_t)b * S_LEN * H_DIM + h * HDIM;
    float* W = w + (size_t)bh * S_LEN * S_LEN;

    __shared__ float As[16][132];
    __shared__ float Bs[16][132];
    __shared__ float sm_m[128];
    __shared__ float sm_il[128];

    const int tid = threadIdx.x;
    const int tx = tid & 15;
    const int ty = tid >> 4;

    float row_m[8], row_l[8];
    #pragma unroll
    for (int i = 0; i < 8; i++) { row_m[i] = -CUDART_INF_F; row_l[i] = 0.0f; }

    // ---------------- Phase 1: scores + online stats ----------------
    for (int kt = 0; kt < 8; kt++) {
        const int n0 = kt * 128;

        unsigned long long acc[8][4];
        #pragma unroll
        for (int i = 0; i < 8; i++)
            #pragma unroll
            for (int j = 0; j < 4; j++) acc[i][j] = 0ull;

        for (int k0 = 0; k0 < HDIM; k0 += 16) {
            #pragma unroll
            for (int l = 0; l < 2; l++) {
                int f = l * 256 + tid;
                int r = f >> 2, c4 = f & 3;
                const float4 v = *reinterpret_cast<const float4*>(
                    Qb + (size_t)(q0 + r) * H_DIM + k0 + c4 * 4);
                As[c4 * 4 + 0][r] = v.x; As[c4 * 4 + 1][r] = v.y;
                As[c4 * 4 + 2][r] = v.z; As[c4 * 4 + 3][r] = v.w;
            }
            #pragma unroll
            for (int l = 0; l < 2; l++) {
                int f = l * 256 + tid;
                int r = f >> 2, c4 = f & 3;
                const float4 v = *reinterpret_cast<const float4*>(
                    Kb + (size_t)(n0 + r) * H_DIM + k0 + c4 * 4);
                Bs[c4 * 4 + 0][r] = v.x; Bs[c4 * 4 + 1][r] = v.y;
                Bs[c4 * 4 + 2][r] = v.z; Bs[c4 * 4 + 3][r] = v.w;
            }
            __syncthreads();

            #pragma unroll
            for (int kk = 0; kk < 16; kk++) {
                float4 a0 = *reinterpret_cast<const float4*>(&As[kk][ty * 8]);
                float4 a1 = *reinterpret_cast<const float4*>(&As[kk][ty * 8 + 4]);
                unsigned long long aa[8];
                aa[0] = pack2(a0.x); aa[1] = pack2(a0.y); aa[2] = pack2(a0.z); aa[3] = pack2(a0.w);
                aa[4] = pack2(a1.x); aa[5] = pack2(a1.y); aa[6] = pack2(a1.z); aa[7] = pack2(a1.w);
                const unsigned long long* bp =
                    reinterpret_cast<const unsigned long long*>(&Bs[kk][tx * 8]);
                unsigned long long b0 = bp[0], b1 = bp[1], b2 = bp[2], b3 = bp[3];
                #pragma unroll
                for (int i = 0; i < 8; i++) {
                    acc[i][0] = ffma2(aa[i], b0, acc[i][0]);
                    acc[i][1] = ffma2(aa[i], b1, acc[i][1]);
                    acc[i][2] = ffma2(aa[i], b2, acc[i][2]);
                    acc[i][3] = ffma2(aa[i], b3, acc[i][3]);
                }
            }
            __syncthreads();
        }

        float madd[8];
        #pragma unroll
        for (int j = 0; j < 8; j++) {
            int n = n0 + tx * 8 + j;
            madd[j] = (mask[b * S_LEN + n] != 0) ? -1000000.0f : 0.0f;
        }

        float sacc[8][8];
        #pragma unroll
        for (int i = 0; i < 8; i++) {
            #pragma unroll
            for (int jj = 0; jj < 4; jj++) {
                float lo, hi;
                unpack2(acc[i][jj], lo, hi);
                sacc[i][2 * jj]     = lo * 0.125f + madd[2 * jj];
                sacc[i][2 * jj + 1] = hi * 0.125f + madd[2 * jj + 1];
            }
        }

        #pragma unroll
        for (int i = 0; i < 8; i++) {
            float tm = sacc[i][0];
            #pragma unroll
            for (int j = 1; j < 8; j++) tm = fmaxf(tm, sacc[i][j]);
            #pragma unroll
            for (int o = 8; o > 0; o >>= 1)
                tm = fmaxf(tm, __shfl_xor_sync(0xffffffffu, tm, o));
            float ts = 0.0f;
            #pragma unroll
            for (int j = 0; j < 8; j++) ts += __expf(sacc[i][j] - tm);
            #pragma unroll
            for (int o = 8; o > 0; o >>= 1)
                ts += __shfl_xor_sync(0xffffffffu, ts, o);

            float mn = fmaxf(row_m[i], tm);
            row_l[i] = row_l[i] * __expf(row_m[i] - mn) + ts * __expf(tm - mn);
            row_m[i] = mn;

            float4 s0 = make_float4(sacc[i][0], sacc[i][1], sacc[i][2], sacc[i][3]);
            float4 s1 = make_float4(sacc[i][4], sacc[i][5], sacc[i][6], sacc[i][7]);
            float* wp = W + (size_t)(q0 + ty * 8 + i) * S_LEN + n0 + tx * 8;
            *reinterpret_cast<float4*>(wp)     = s0;
            *reinterpret_cast<float4*>(wp + 4) = s1;
        }
    }

    if (tx == 0) {
        #pragma unroll
        for (int i = 0; i < 8; i++) {
            sm_m[ty * 8 + i]  = row_m[i];
            sm_il[ty * 8 + i] = 1.0f / row_l[i];
        }
    }
    __syncthreads();

    // ---------------- Phase 2: normalize + P*V ------
    unsigned long long cacc[8][2];
    #pragma unroll
    for (int i = 0; i < 8; i++) { cacc[i][0] = 0ull; cacc[i][1] = 0ull; }

    for (int k0 = 0; k0 < S_LEN; k0 += 16) {
        #pragma unroll
        for (int l = 0; l < 2; l++) {
            int f = l * 256 + tid;
            int r = f >> 2, c4 = f & 3;
            float* wp = W + (size_t)(q0 + r) * S_LEN + k0 + c4 * 4;
            float4 v = *reinterpret_cast<const float4*>(wp);
            const float mm = sm_m[r];
            const float il = sm_il[r];
            v.x = __expf(v.x - mm) * il;
            v.y = __expf(v.y - mm) * il;
            v.z = __expf(v.z - mm) * il;
            v.w = __expf(v.w - mm) * il;
            *reinterpret_cast<float4*>(wp) = v;
            As[c4 * 4 + 0][r] = v.x; As[c4 * 4 + 1][r] = v.y;
            As[c4 * 4 + 2][r] = v.z; As[c4 * 4 + 3][r] = v.w;
        }
        {
            int r = tid >> 4, c4 = tid & 15;
            const float4 v = *reinterpret_cast<const float4*>(
                Vb + (size_t)(k0 + r) * H_DIM + c4 * 4);
            *reinterpret_cast<float4*>(&Bs[r][c4 * 4]) = v;
        }
        __syncthreads();

        #pragma unroll
        for (int kk = 0; kk < 16; kk++) {
            float4 a0 = *reinterpret_cast<const float4*>(&As[kk][ty * 8]);
            float4 a1 = *reinterpret_cast<const float4*>(&As[kk][ty * 8 + 4]);
            unsigned long long aa[8];
            aa[0] = pack2(a0.x); aa[1] = pack2(a0.y); aa[2] = pack2(a0.z); aa[3] = pack2(a0.w);
            aa[4] = pack2(a1.x); aa[5] = pack2(a1.y); aa[6] = pack2(a1.z); aa[7] = pack2(a1.w);
            const unsigned long long* bp =
                reinterpret_cast<const unsigned long long*>(&Bs[kk][tx * 4]);
            unsigned long long b0 = bp[0], b1 = bp[1];
            #pragma unroll
            for (int i = 0; i < 8; i++) {
                cacc[i][0] = ffma2(aa[i], b0, cacc[i][0]);
                cacc[i][1] = ffma2(aa[i], b1, cacc[i][1]);
            }
        }
        __syncthreads();
    }

    #pragma unroll
    for (int i = 0; i < 8; i++) {
        int s = q0 + ty * 8 + i;
        float lo, hi;
        float4 o;
        unpack2(cacc[i][0], lo, hi); o.x = lo; o.y = hi;
        unpack2(cacc[i][1], lo, hi); o.z = lo; o.w = hi;
        *reinterpret_cast<float4*>(
            out_ctx + ((size_t)s * B_SZ + b) * H_DIM + h * HDIM + tx * 4) = o;
    }
}

// ---------------------------------------------------------------------------
// Launch
// ---------------------------------------------------------------------------
extern "C" void kernel_launch(void* const* d_in, const int* in_sizes, int n_in,
                              void* d_out, int out_size)
{
    const float* q_states = (const float*)d_in[0];
    const float* k_states = (const float*)d_in[1];
    const float* v_states = (const float*)d_in[2];
    const int*   mask     = (const int*)  d_in[3];
    const float* Wq = (const float*)d_in[4];
    const float* bq = (const float*)d_in[5];
    const float* Wk = (const float*)d_in[6];
    const float* bk = (const float*)d_in[7];
    const float* Wv = (const float*)d_in[8];
    const float* bv = (const float*)d_in[9];

    float* out_ctx = (float*)d_out;                           // [S, B, H]
    float* out_w   = out_ctx + (size_t)S_LEN * B_SZ * H_DIM;  // [B, NH, S, S]

    dim3 pg(H_DIM / 128, M_ROWS / 128, 3);   // (8, 64, 3) — one merged launch
    proj_kernel<<<pg, 256>>>(
        q_states, k_states, v_states, Wq, bq, Wk, bk, Wv, bv);

    dim3 ag(S_LEN / 128, B_SZ * NHEAD);      // (8, 128)
    attn_kernel<<<ag, 256>>>(mask, out_w, out_ctx);
}